// round 3
// baseline (speedup 1.0000x reference)
#include <cuda_runtime.h>
#include <cstdint>

#define TOT    400000
#define NPTS   50000
#define NBLK   5
#define PTS    128          // points per CTA
#define XSTR   68           // padded activation row stride (floats)

typedef unsigned long long ull;

// Per-batch conditioning: cond[b][i][h] = task_feature[b] @ fc_c_W[i][64:576,:] + fc_c_b[i]
__device__ float g_cond[8 * NBLK * 64];

// ---------- packed f32x2 helpers ----------
__device__ __forceinline__ ull dup2(float x) {
    ull r; asm("mov.b64 %0, {%1, %1};" : "=l"(r) : "f"(x)); return r;
}
__device__ __forceinline__ float2 unpk(ull a) {
    float2 f; asm("mov.b64 {%0, %1}, %2;" : "=f"(f.x), "=f"(f.y) : "l"(a)); return f;
}
__device__ __forceinline__ void fma2(ull &a, ull x, ull w) {
    asm("fma.rn.f32x2 %0, %1, %2, %0;" : "+l"(a) : "l"(x), "l"(w));
}
__device__ __forceinline__ void add2(ull &a, ull b) {
    asm("add.rn.f32x2 %0, %0, %1;" : "+l"(a) : "l"(b));
}

// ---------- shared layout (float offsets) ----------
#define OFF_W     0        // 3 * 64*64 (Wc @0, W0 @4096, W1 @8192)
#define OFF_NET   12288    // 128 * 68
#define OFF_H     20992    // 128 * 68
#define OFF_CB    29696    // 128 * 68
#define OFF_COND  38400    // 8*5*64
#define OFF_PW    40960    // 192
#define OFF_PB    41152    // 64
#define OFF_OW    41216    // 768
#define OFF_OB    41984    // 16
#define OFF_B0    42000    // 64
#define OFF_B1    42064    // 64
#define SM_FLOATS 42128
#define SM_BYTES  (SM_FLOATS * 4)

// ---------- conditioning precompute ----------
__global__ void cond_kernel(const float* __restrict__ tf,
                            const float* __restrict__ fc_c_W,
                            const float* __restrict__ fc_c_b) {
    int bi = blockIdx.x;          // b*5 + i
    int b  = bi / NBLK, i = bi % NBLK;
    int h  = threadIdx.x & 63, g = threadIdx.x >> 6;
    const float* W = fc_c_W + (size_t)i * 576 * 64 + 64 * 64 + h;
    const float* t = tf + b * 512;
    float acc = 0.f;
    int k0 = g * 128;
    #pragma unroll 8
    for (int k = k0; k < k0 + 128; k++) acc += t[k] * W[(size_t)k * 64];
    __shared__ float red[256];
    red[threadIdx.x] = acc;
    __syncthreads();
    if (g == 0) {
        float s = red[h] + red[h + 64] + red[h + 128] + red[h + 192] + fc_c_b[i * 64 + h];
        g_cond[bi * 64 + h] = s;
    }
}

// 64-k GEMM microtile: acc[q][0..3] (8 outputs as 4 f32x2) for 4 points
__device__ __forceinline__ void mm64(ull acc[4][4], const float* __restrict__ xb,
                                     const float* __restrict__ Wog, bool relu_x) {
    #pragma unroll 2
    for (int kk = 0; kk < 64; kk += 4) {
        float xa[4][4];
        *(float4*)xa[0] = *(const float4*)(xb + 0 * XSTR + kk);
        *(float4*)xa[1] = *(const float4*)(xb + 1 * XSTR + kk);
        *(float4*)xa[2] = *(const float4*)(xb + 2 * XSTR + kk);
        *(float4*)xa[3] = *(const float4*)(xb + 3 * XSTR + kk);
        if (relu_x) {
            #pragma unroll
            for (int q = 0; q < 4; q++)
                #pragma unroll
                for (int d = 0; d < 4; d++) xa[q][d] = fmaxf(xa[q][d], 0.f);
        }
        #pragma unroll
        for (int d = 0; d < 4; d++) {
            ulonglong2 wA = *(const ulonglong2*)(Wog + (kk + d) * 64);
            ulonglong2 wB = *(const ulonglong2*)(Wog + (kk + d) * 64 + 4);
            #pragma unroll
            for (int q = 0; q < 4; q++) {
                ull xd = dup2(xa[q][d]);
                fma2(acc[q][0], xd, wA.x);
                fma2(acc[q][1], xd, wA.y);
                fma2(acc[q][2], xd, wB.x);
                fma2(acc[q][3], xd, wB.y);
            }
        }
    }
}

__global__ __launch_bounds__(256, 1)
void mlp_kernel(const float* __restrict__ p, const float* __restrict__ c,
                const float* __restrict__ fc_p_W, const float* __restrict__ fc_p_b,
                const float* __restrict__ fc_c_W,
                const float* __restrict__ blk0_W, const float* __restrict__ blk0_b,
                const float* __restrict__ blk1_W, const float* __restrict__ blk1_b,
                const float* __restrict__ fc_out_W, const float* __restrict__ fc_out_b,
                float* __restrict__ out) {
    extern __shared__ float sm[];
    const int tid = threadIdx.x;
    const int og  = tid & 7;         // output group: cols og*8 .. og*8+7
    const int pg  = tid >> 3;        // point group: rows pg*4 .. pg*4+3
    const int base = blockIdx.x * PTS;
    const int p0i  = base + pg * 4;

    // one-time param loads
    for (int w = tid; w < 192; w += 256) sm[OFF_PW + w] = fc_p_W[w];
    if (tid < 64) sm[OFF_PB + tid] = fc_p_b[tid];
    for (int w = tid; w < 768; w += 256) sm[OFF_OW + w] = fc_out_W[w];
    if (tid < 12) sm[OFF_OB + tid] = fc_out_b[tid];
    if (tid >= 12 && tid < 16) sm[OFF_OB + tid] = 0.f;
    for (int w = tid; w < 8 * NBLK * 64; w += 256) sm[OFF_COND + w] = g_cond[w];

    // per-thread point coords + cond base offsets
    float pv[4][3];
    int   cbase[4];
    #pragma unroll
    for (int q = 0; q < 4; q++) {
        #pragma unroll
        for (int e = 0; e < 3; e++) pv[q][e] = p[(size_t)(p0i + q) * 3 + e];
        cbase[q] = ((p0i + q) / NPTS) * (NBLK * 64) + og * 8;
    }

    // stage point codes c -> cbuf (stride-68 rows)
    {
        const float4* src = (const float4*)(c + (size_t)base * 64);
        #pragma unroll
        for (int t = 0; t < 8; t++) {
            int w = tid + t * 256;
            float4 v = src[w];
            int pt = w >> 4, e = (w & 15) << 2;
            *(float4*)(sm + OFF_CB + pt * XSTR + e) = v;
        }
    }

    const float* xc = sm + OFF_CB  + pg * 4 * XSTR;
    const float* xn = sm + OFF_NET + pg * 4 * XSTR;
    const float* xh = sm + OFF_H   + pg * 4 * XSTR;
    float* wn = sm + OFF_NET + pg * 4 * XSTR + og * 8;
    float* wh = sm + OFF_H   + pg * 4 * XSTR + og * 8;

    for (int i = 0; i < NBLK; i++) {
        __syncthreads();
        // load this block's weights into shared
        {
            const float4* wc = (const float4*)(fc_c_W + (size_t)i * 576 * 64); // rows 0..63 = c-part
            const float4* w0 = (const float4*)(blk0_W + (size_t)i * 4096);
            const float4* w1 = (const float4*)(blk1_W + (size_t)i * 4096);
            float4* dW = (float4*)(sm + OFF_W);
            #pragma unroll
            for (int w = 0; w < 4; w++) {
                dW[tid + w * 256]        = wc[tid + w * 256];
                dW[1024 + tid + w * 256] = w0[tid + w * 256];
                dW[2048 + tid + w * 256] = w1[tid + w * 256];
            }
            if (tid < 64) {
                sm[OFF_B0 + tid] = blk0_b[i * 64 + tid];
                sm[OFF_B1 + tid] = blk1_b[i * 64 + tid];
            }
        }
        __syncthreads();

        ull acc[4][4];
        // ---- step 1: net = prev_net (or p-layer) + cond + c @ Wc ----
        if (i == 0) {
            ulonglong2 pbA = *(const ulonglong2*)(sm + OFF_PB + og * 8);
            ulonglong2 pbB = *(const ulonglong2*)(sm + OFF_PB + og * 8 + 4);
            #pragma unroll
            for (int q = 0; q < 4; q++) {
                acc[q][0] = pbA.x; acc[q][1] = pbA.y; acc[q][2] = pbB.x; acc[q][3] = pbB.y;
            }
            #pragma unroll
            for (int e = 0; e < 3; e++) {
                ulonglong2 wA = *(const ulonglong2*)(sm + OFF_PW + e * 64 + og * 8);
                ulonglong2 wB = *(const ulonglong2*)(sm + OFF_PW + e * 64 + og * 8 + 4);
                #pragma unroll
                for (int q = 0; q < 4; q++) {
                    ull xd = dup2(pv[q][e]);
                    fma2(acc[q][0], xd, wA.x); fma2(acc[q][1], xd, wA.y);
                    fma2(acc[q][2], xd, wB.x); fma2(acc[q][3], xd, wB.y);
                }
            }
        } else {
            #pragma unroll
            for (int q = 0; q < 4; q++) {
                ulonglong2 a = *(const ulonglong2*)(xn + q * XSTR + og * 8);
                ulonglong2 b = *(const ulonglong2*)(xn + q * XSTR + og * 8 + 4);
                acc[q][0] = a.x; acc[q][1] = a.y; acc[q][2] = b.x; acc[q][3] = b.y;
            }
        }
        #pragma unroll
        for (int q = 0; q < 4; q++) {
            const ulonglong2* cd = (const ulonglong2*)(sm + OFF_COND + cbase[q] + i * 64);
            ulonglong2 c0 = cd[0], c1 = cd[1];
            add2(acc[q][0], c0.x); add2(acc[q][1], c0.y);
            add2(acc[q][2], c1.x); add2(acc[q][3], c1.y);
        }
        mm64(acc, xc, sm + OFF_W + og * 8, false);
        #pragma unroll
        for (int q = 0; q < 4; q++) {
            ulonglong2 s0, s1;
            s0.x = acc[q][0]; s0.y = acc[q][1]; s1.x = acc[q][2]; s1.y = acc[q][3];
            *(ulonglong2*)(wn + q * XSTR)     = s0;
            *(ulonglong2*)(wn + q * XSTR + 4) = s1;
        }
        __syncthreads();

        // ---- step 2: h = relu(net) @ W0 + b0 ; store relu(h) ----
        {
            ulonglong2 bA = *(const ulonglong2*)(sm + OFF_B0 + og * 8);
            ulonglong2 bB = *(const ulonglong2*)(sm + OFF_B0 + og * 8 + 4);
            #pragma unroll
            for (int q = 0; q < 4; q++) {
                acc[q][0] = bA.x; acc[q][1] = bA.y; acc[q][2] = bB.x; acc[q][3] = bB.y;
            }
            mm64(acc, xn, sm + OFF_W + 4096 + og * 8, true);
            #pragma unroll
            for (int q = 0; q < 4; q++) {
                float2 f0 = unpk(acc[q][0]), f1 = unpk(acc[q][1]);
                float2 f2 = unpk(acc[q][2]), f3 = unpk(acc[q][3]);
                float4 r0 = make_float4(fmaxf(f0.x, 0.f), fmaxf(f0.y, 0.f),
                                        fmaxf(f1.x, 0.f), fmaxf(f1.y, 0.f));
                float4 r1 = make_float4(fmaxf(f2.x, 0.f), fmaxf(f2.y, 0.f),
                                        fmaxf(f3.x, 0.f), fmaxf(f3.y, 0.f));
                *(float4*)(wh + q * XSTR)     = r0;
                *(float4*)(wh + q * XSTR + 4) = r1;
            }
        }
        __syncthreads();

        // ---- step 3: net += relu(h) @ W1 + b1 ----
        {
            ulonglong2 bA = *(const ulonglong2*)(sm + OFF_B1 + og * 8);
            ulonglong2 bB = *(const ulonglong2*)(sm + OFF_B1 + og * 8 + 4);
            #pragma unroll
            for (int q = 0; q < 4; q++) {
                ulonglong2 a = *(const ulonglong2*)(xn + q * XSTR + og * 8);
                ulonglong2 b = *(const ulonglong2*)(xn + q * XSTR + og * 8 + 4);
                acc[q][0] = a.x; acc[q][1] = a.y; acc[q][2] = b.x; acc[q][3] = b.y;
                add2(acc[q][0], bA.x); add2(acc[q][1], bA.y);
                add2(acc[q][2], bB.x); add2(acc[q][3], bB.y);
            }
            mm64(acc, xh, sm + OFF_W + 8192 + og * 8, false);
            #pragma unroll
            for (int q = 0; q < 4; q++) {
                ulonglong2 s0, s1;
                s0.x = acc[q][0]; s0.y = acc[q][1]; s1.x = acc[q][2]; s1.y = acc[q][3];
                *(ulonglong2*)(wn + q * XSTR)     = s0;
                *(ulonglong2*)(wn + q * XSTR + 4) = s1;
            }
        }
    }
    __syncthreads();

    // ---- out = relu(net) @ fc_out_W + fc_out_b ; one point per thread (tid<128) ----
    if (tid < PTS) {
        ull o[6];
        const ull* ob = (const ull*)(sm + OFF_OB);
        #pragma unroll
        for (int j = 0; j < 6; j++) o[j] = ob[j];
        const float* xr = sm + OFF_NET + tid * XSTR;
        #pragma unroll 2
        for (int kk = 0; kk < 64; kk += 4) {
            float xa[4];
            *(float4*)xa = *(const float4*)(xr + kk);
            #pragma unroll
            for (int d = 0; d < 4; d++) {
                ull xd = dup2(fmaxf(xa[d], 0.f));
                const ull* wr = (const ull*)(sm + OFF_OW + (kk + d) * 12);
                #pragma unroll
                for (int j = 0; j < 6; j++) fma2(o[j], xd, wr[j]);
            }
        }
        float2 f0 = unpk(o[0]), f1 = unpk(o[1]), f2 = unpk(o[2]);
        float2 f3 = unpk(o[3]), f4 = unpk(o[4]), f5 = unpk(o[5]);
        float4* dst = (float4*)(out + (size_t)(base + tid) * 12);
        dst[0] = make_float4(f0.x, f0.y, f1.x, f1.y);
        dst[1] = make_float4(f2.x, f2.y, f3.x, f3.y);
        dst[2] = make_float4(f4.x, f4.y, f5.x, f5.y);
    }
}

extern "C" void kernel_launch(void* const* d_in, const int* in_sizes, int n_in,
                              void* d_out, int out_size) {
    const float* p        = (const float*)d_in[0];
    const float* c        = (const float*)d_in[1];
    const float* tf       = (const float*)d_in[2];
    const float* fc_p_W   = (const float*)d_in[3];
    const float* fc_p_b   = (const float*)d_in[4];
    const float* fc_c_W   = (const float*)d_in[5];
    const float* fc_c_b   = (const float*)d_in[6];
    const float* blk0_W   = (const float*)d_in[7];
    const float* blk0_b   = (const float*)d_in[8];
    const float* blk1_W   = (const float*)d_in[9];
    const float* blk1_b   = (const float*)d_in[10];
    const float* fc_out_W = (const float*)d_in[11];
    const float* fc_out_b = (const float*)d_in[12];
    float* out = (float*)d_out;

    cudaFuncSetAttribute(mlp_kernel, cudaFuncAttributeMaxDynamicSharedMemorySize, SM_BYTES);

    cond_kernel<<<8 * NBLK, 256>>>(tf, fc_c_W, fc_c_b);

    int grid = TOT / PTS;   // 3125 CTAs, 128 points each (exact)
    mlp_kernel<<<grid, 256, SM_BYTES>>>(p, c, fc_p_W, fc_p_b, fc_c_W,
                                        blk0_W, blk0_b, blk1_W, blk1_b,
                                        fc_out_W, fc_out_b, out);
}

// round 4
// speedup vs baseline: 1.6935x; 1.6935x over previous
#include <cuda_runtime.h>
#include <cstdint>

#define TOT    400000
#define NPTS   50000
#define NBLK   5
#define PTS    128          // points per CTA
#define XSTR   68           // activation row stride (floats): 4-bank shift per row

typedef unsigned long long ull;

// Per-batch conditioning: cond[b][i][h] = task_feature[b] @ fc_c_W[i][64:576,:] + fc_c_b[i]
__device__ float g_cond[8 * NBLK * 64];

// ---------- packed f32x2 helpers ----------
__device__ __forceinline__ ull dup2(float x) {
    ull r; asm("mov.b64 %0, {%1, %1};" : "=l"(r) : "f"(x)); return r;
}
__device__ __forceinline__ float2 unpk(ull a) {
    float2 f; asm("mov.b64 {%0, %1}, %2;" : "=f"(f.x), "=f"(f.y) : "l"(a)); return f;
}
__device__ __forceinline__ void fma2(ull &a, ull x, ull w) {
    asm("fma.rn.f32x2 %0, %1, %2, %0;" : "+l"(a) : "l"(x), "l"(w));
}
__device__ __forceinline__ void add2(ull &a, ull b) {
    asm("add.rn.f32x2 %0, %0, %1;" : "+l"(a) : "l"(b));
}

// ---------- cp.async helpers ----------
__device__ __forceinline__ void cpa16(uint32_t dst, const float* src) {
    asm volatile("cp.async.cg.shared.global [%0], [%1], 16;" :: "r"(dst), "l"(src));
}
__device__ __forceinline__ void cpa_commit() {
    asm volatile("cp.async.commit_group;");
}
template<int N> __device__ __forceinline__ void cpa_wait() {
    asm volatile("cp.async.wait_group %0;" :: "n"(N));
}

// 16KB weight tile (64x64 f32), 4 x 16B per thread
__device__ __forceinline__ void load_w16(float* dst, const float* src, int tid) {
    uint32_t d = (uint32_t)__cvta_generic_to_shared(dst);
    #pragma unroll
    for (int t = 0; t < 4; t++) {
        int w = tid + t * 256;
        cpa16(d + w * 16, src + w * 4);
    }
}
// 32KB codes -> X (128 rows x XSTR), 8 x 16B per thread
__device__ __forceinline__ void load_codes(float* X, const float* src, int tid) {
    uint32_t d = (uint32_t)__cvta_generic_to_shared(X);
    #pragma unroll
    for (int t = 0; t < 8; t++) {
        int w = tid + t * 256;
        int pt = w >> 4, e = w & 15;
        cpa16(d + (pt * XSTR + e * 4) * 4, src + w * 4);
    }
}

// ---------- shared layout (float offsets) ----------
#define OFF_WA    0        // 4096
#define OFF_WB    4096     // 4096
#define OFF_NET   8192     // 128*68 = 8704
#define OFF_X     16896    // 8704 (codes OR relu(h))
#define OFF_PW    25600    // 192
#define OFF_PB    25792    // 64
#define OFF_OW    25856    // 768
#define OFF_OB    26624    // 16
#define SM_FLOATS 26640
#define SM_BYTES  (SM_FLOATS * 4)   // 106560 B -> 2 CTAs/SM

// ---------- conditioning precompute ----------
__global__ void cond_kernel(const float* __restrict__ tf,
                            const float* __restrict__ fc_c_W,
                            const float* __restrict__ fc_c_b) {
    int bi = blockIdx.x;          // b*5 + i
    int b  = bi / NBLK, i = bi % NBLK;
    int h  = threadIdx.x & 63, g = threadIdx.x >> 6;
    const float* W = fc_c_W + (size_t)i * 576 * 64 + 64 * 64 + h;
    const float* t = tf + b * 512;
    float acc = 0.f;
    int k0 = g * 128;
    #pragma unroll 8
    for (int k = k0; k < k0 + 128; k++) acc += t[k] * W[(size_t)k * 64];
    __shared__ float red[256];
    red[threadIdx.x] = acc;
    __syncthreads();
    if (g == 0) {
        float s = red[h] + red[h + 64] + red[h + 128] + red[h + 192] + fc_c_b[i * 64 + h];
        g_cond[bi * 64 + h] = s;
    }
}

// GEMM microtile: 4 points x 8 cols ({og*4..+3} and {32+og*4..+3})
// Wt = weight base + og*4; xb = act base + pg*XSTR; rows at q*32*XSTR
__device__ __forceinline__ void mm64(ull acc[4][4], const float* __restrict__ xb,
                                     const float* __restrict__ Wt, bool relu_x) {
    #pragma unroll 2
    for (int kk = 0; kk < 64; kk += 4) {
        float xa[4][4];
        #pragma unroll
        for (int q = 0; q < 4; q++)
            *(float4*)xa[q] = *(const float4*)(xb + q * 32 * XSTR + kk);
        if (relu_x) {
            #pragma unroll
            for (int q = 0; q < 4; q++)
                #pragma unroll
                for (int d = 0; d < 4; d++) xa[q][d] = fmaxf(xa[q][d], 0.f);
        }
        #pragma unroll
        for (int d = 0; d < 4; d++) {
            ulonglong2 wA = *(const ulonglong2*)(Wt + (kk + d) * 64);
            ulonglong2 wB = *(const ulonglong2*)(Wt + (kk + d) * 64 + 32);
            #pragma unroll
            for (int q = 0; q < 4; q++) {
                ull xd = dup2(xa[q][d]);
                fma2(acc[q][0], xd, wA.x);
                fma2(acc[q][1], xd, wA.y);
                fma2(acc[q][2], xd, wB.x);
                fma2(acc[q][3], xd, wB.y);
            }
        }
    }
}

__global__ __launch_bounds__(256, 2)
void mlp_kernel(const float* __restrict__ p, const float* __restrict__ c,
                const float* __restrict__ fc_p_W, const float* __restrict__ fc_p_b,
                const float* __restrict__ fc_c_W,
                const float* __restrict__ blk0_W, const float* __restrict__ blk0_b,
                const float* __restrict__ blk1_W, const float* __restrict__ blk1_b,
                const float* __restrict__ fc_out_W, const float* __restrict__ fc_out_b,
                float* __restrict__ out) {
    extern __shared__ float sm[];
    const int tid = threadIdx.x;
    const int og  = tid & 7;          // col group: cols og*4..+3 and 32+og*4..+3
    const int pg  = tid >> 3;         // row group: rows pg, pg+32, pg+64, pg+96
    const int base = blockIdx.x * PTS;

    float* WA   = sm + OFF_WA;
    float* WB   = sm + OFF_WB;
    float* NETB = sm + OFF_NET;
    float* X    = sm + OFF_X;

    // prologue async loads: Wc_0 -> WA, codes -> X
    load_w16(WA, fc_c_W, tid); cpa_commit();
    load_codes(X, c + (size_t)base * 64, tid); cpa_commit();

    // small params -> smem
    for (int w = tid; w < 192; w += 256) sm[OFF_PW + w] = fc_p_W[w];
    if (tid < 64) sm[OFF_PB + tid] = fc_p_b[tid];
    for (int w = tid; w < 768; w += 256) sm[OFF_OW + w] = fc_out_W[w];
    if (tid < 16) sm[OFF_OB + tid] = (tid < 12) ? fc_out_b[tid] : 0.f;

    // per-thread: point coords + cond offsets
    float pv[4][3];
    int   cnd[4];
    #pragma unroll
    for (int q = 0; q < 4; q++) {
        int pt = base + pg + q * 32;
        #pragma unroll
        for (int e = 0; e < 3; e++) pv[q][e] = p[(size_t)pt * 3 + e];
        cnd[q] = (pt / NPTS) * (NBLK * 64) + og * 4;
    }

    const float* xb = X    + pg * XSTR;          // x source: codes (s1) / relu(h) (s3)
    const float* nb = NETB + pg * XSTR;          // x source: net (s2)
    float* wrN = NETB + pg * XSTR + og * 4;      // this thread's net tile
    float* wrX = X    + pg * XSTR + og * 4;      // this thread's h tile

    for (int i = 0; i < NBLK; i++) {
        float* Wcur = (i & 1) ? WB : WA;
        float* Woth = (i & 1) ? WA : WB;

        // codes for this block (X was clobbered by h last block); W0 prefetch
        if (i > 0) { load_codes(X, c + (size_t)base * 64, tid); cpa_commit(); }
        load_w16(Woth, blk0_W + (size_t)i * 4096, tid); cpa_commit();
        cpa_wait<1>();            // Wc_i + codes done; W0 may still fly
        __syncthreads();

        ull acc[4][4];
        // ---- step1: net = (p-layer | prev net) + cond + c @ Wc ----
        if (i == 0) {
            ulonglong2 pbA = *(const ulonglong2*)(sm + OFF_PB + og * 4);
            ulonglong2 pbB = *(const ulonglong2*)(sm + OFF_PB + og * 4 + 32);
            #pragma unroll
            for (int q = 0; q < 4; q++) {
                acc[q][0] = pbA.x; acc[q][1] = pbA.y; acc[q][2] = pbB.x; acc[q][3] = pbB.y;
            }
            #pragma unroll
            for (int e = 0; e < 3; e++) {
                ulonglong2 wA = *(const ulonglong2*)(sm + OFF_PW + e * 64 + og * 4);
                ulonglong2 wB = *(const ulonglong2*)(sm + OFF_PW + e * 64 + og * 4 + 32);
                #pragma unroll
                for (int q = 0; q < 4; q++) {
                    ull xd = dup2(pv[q][e]);
                    fma2(acc[q][0], xd, wA.x); fma2(acc[q][1], xd, wA.y);
                    fma2(acc[q][2], xd, wB.x); fma2(acc[q][3], xd, wB.y);
                }
            }
        } else {
            #pragma unroll
            for (int q = 0; q < 4; q++) {
                ulonglong2 a = *(const ulonglong2*)(wrN + q * 32 * XSTR);
                ulonglong2 b = *(const ulonglong2*)(wrN + q * 32 * XSTR + 32);
                acc[q][0] = a.x; acc[q][1] = a.y; acc[q][2] = b.x; acc[q][3] = b.y;
            }
        }
        #pragma unroll
        for (int q = 0; q < 4; q++) {
            ulonglong2 c0 = __ldg((const ulonglong2*)(g_cond + cnd[q] + i * 64));
            ulonglong2 c1 = __ldg((const ulonglong2*)(g_cond + cnd[q] + i * 64 + 32));
            add2(acc[q][0], c0.x); add2(acc[q][1], c0.y);
            add2(acc[q][2], c1.x); add2(acc[q][3], c1.y);
        }
        mm64(acc, xb, Wcur + og * 4, false);
        #pragma unroll
        for (int q = 0; q < 4; q++) {
            ulonglong2 s0, s1;
            s0.x = acc[q][0]; s0.y = acc[q][1]; s1.x = acc[q][2]; s1.y = acc[q][3];
            *(ulonglong2*)(wrN + q * 32 * XSTR)      = s0;
            *(ulonglong2*)(wrN + q * 32 * XSTR + 32) = s1;
        }
        cpa_wait<0>();            // W0_i arrived
        __syncthreads();

        // ---- step2: h = relu(net) @ W0 + b0 ; write relu(h) -> X ----
        load_w16(Wcur, blk1_W + (size_t)i * 4096, tid); cpa_commit();  // W1 prefetch
        {
            ulonglong2 bA = __ldg((const ulonglong2*)(blk0_b + i * 64 + og * 4));
            ulonglong2 bB = __ldg((const ulonglong2*)(blk0_b + i * 64 + og * 4 + 32));
            #pragma unroll
            for (int q = 0; q < 4; q++) {
                acc[q][0] = bA.x; acc[q][1] = bA.y; acc[q][2] = bB.x; acc[q][3] = bB.y;
            }
            mm64(acc, nb, Woth + og * 4, true);
            #pragma unroll
            for (int q = 0; q < 4; q++) {
                float2 f0 = unpk(acc[q][0]), f1 = unpk(acc[q][1]);
                float2 f2 = unpk(acc[q][2]), f3 = unpk(acc[q][3]);
                *(float4*)(wrX + q * 32 * XSTR) =
                    make_float4(fmaxf(f0.x, 0.f), fmaxf(f0.y, 0.f),
                                fmaxf(f1.x, 0.f), fmaxf(f1.y, 0.f));
                *(float4*)(wrX + q * 32 * XSTR + 32) =
                    make_float4(fmaxf(f2.x, 0.f), fmaxf(f2.y, 0.f),
                                fmaxf(f3.x, 0.f), fmaxf(f3.y, 0.f));
            }
        }
        cpa_wait<0>();            // W1_i arrived
        __syncthreads();

        // ---- step3: net += relu(h) @ W1 + b1 ----
        if (i < NBLK - 1) { load_w16(Woth, fc_c_W + (size_t)(i + 1) * 576 * 64, tid); cpa_commit(); }
        {
            ulonglong2 bA = __ldg((const ulonglong2*)(blk1_b + i * 64 + og * 4));
            ulonglong2 bB = __ldg((const ulonglong2*)(blk1_b + i * 64 + og * 4 + 32));
            #pragma unroll
            for (int q = 0; q < 4; q++) {
                ulonglong2 a = *(const ulonglong2*)(wrN + q * 32 * XSTR);
                ulonglong2 b = *(const ulonglong2*)(wrN + q * 32 * XSTR + 32);
                acc[q][0] = a.x; acc[q][1] = a.y; acc[q][2] = b.x; acc[q][3] = b.y;
                add2(acc[q][0], bA.x); add2(acc[q][1], bA.y);
                add2(acc[q][2], bB.x); add2(acc[q][3], bB.y);
            }
            mm64(acc, xb, Wcur + og * 4, false);
            #pragma unroll
            for (int q = 0; q < 4; q++) {
                ulonglong2 s0, s1;
                s0.x = acc[q][0]; s0.y = acc[q][1]; s1.x = acc[q][2]; s1.y = acc[q][3];
                *(ulonglong2*)(wrN + q * 32 * XSTR)      = s0;
                *(ulonglong2*)(wrN + q * 32 * XSTR + 32) = s1;
            }
        }
        __syncthreads();
    }

    // ---- out = relu(net) @ fc_out_W + fc_out_b ; one point per thread (tid<128) ----
    if (tid < PTS) {
        ull o[6];
        const ull* ob = (const ull*)(sm + OFF_OB);
        #pragma unroll
        for (int j = 0; j < 6; j++) o[j] = ob[j];
        const float* xr = NETB + tid * XSTR;
        #pragma unroll 2
        for (int kk = 0; kk < 64; kk += 4) {
            float xa[4];
            *(float4*)xa = *(const float4*)(xr + kk);
            #pragma unroll
            for (int d = 0; d < 4; d++) {
                ull xd = dup2(fmaxf(xa[d], 0.f));
                const ull* wr = (const ull*)(sm + OFF_OW + (kk + d) * 12);
                #pragma unroll
                for (int j = 0; j < 6; j++) fma2(o[j], xd, wr[j]);
            }
        }
        float2 f0 = unpk(o[0]), f1 = unpk(o[1]), f2 = unpk(o[2]);
        float2 f3 = unpk(o[3]), f4 = unpk(o[4]), f5 = unpk(o[5]);
        float4* dst = (float4*)(out + (size_t)(base + tid) * 12);
        dst[0] = make_float4(f0.x, f0.y, f1.x, f1.y);
        dst[1] = make_float4(f2.x, f2.y, f3.x, f3.y);
        dst[2] = make_float4(f4.x, f4.y, f5.x, f5.y);
    }
}

extern "C" void kernel_launch(void* const* d_in, const int* in_sizes, int n_in,
                              void* d_out, int out_size) {
    const float* p        = (const float*)d_in[0];
    const float* c        = (const float*)d_in[1];
    const float* tf       = (const float*)d_in[2];
    const float* fc_p_W   = (const float*)d_in[3];
    const float* fc_p_b   = (const float*)d_in[4];
    const float* fc_c_W   = (const float*)d_in[5];
    const float* fc_c_b   = (const float*)d_in[6];
    const float* blk0_W   = (const float*)d_in[7];
    const float* blk0_b   = (const float*)d_in[8];
    const float* blk1_W   = (const float*)d_in[9];
    const float* blk1_b   = (const float*)d_in[10];
    const float* fc_out_W = (const float*)d_in[11];
    const float* fc_out_b = (const float*)d_in[12];
    float* out = (float*)d_out;

    cudaFuncSetAttribute(mlp_kernel, cudaFuncAttributeMaxDynamicSharedMemorySize, SM_BYTES);

    cond_kernel<<<8 * NBLK, 256>>>(tf, fc_c_W, fc_c_b);

    int grid = TOT / PTS;   // 3125 CTAs, 128 points each (exact)
    mlp_kernel<<<grid, 256, SM_BYTES>>>(p, c, fc_p_W, fc_p_b, fc_c_W,
                                        blk0_W, blk0_b, blk1_W, blk1_b,
                                        fc_out_W, fc_out_b, out);
}

// round 5
// speedup vs baseline: 1.7368x; 1.0255x over previous
#include <cuda_runtime.h>
#include <cstdint>

#define TOT    400000
#define NPTS   50000
#define NBLK   5
#define PTS    128          // points per CTA
#define THR    128          // threads per CTA
#define XSTR   68           // activation row stride (floats)

typedef unsigned long long ull;

// Per-batch conditioning: cond[b][i][h] = task_feature[b] @ fc_c_W[i][64:576,:] + fc_c_b[i]
__device__ float g_cond[8 * NBLK * 64];

// ---------- packed f32x2 helpers ----------
__device__ __forceinline__ ull dup2(float x) {
    ull r; asm("mov.b64 %0, {%1, %1};" : "=l"(r) : "f"(x)); return r;
}
__device__ __forceinline__ float2 unpk(ull a) {
    float2 f; asm("mov.b64 {%0, %1}, %2;" : "=f"(f.x), "=f"(f.y) : "l"(a)); return f;
}
__device__ __forceinline__ void fma2(ull &a, ull x, ull w) {
    asm("fma.rn.f32x2 %0, %1, %2, %0;" : "+l"(a) : "l"(x), "l"(w));
}
__device__ __forceinline__ void add2(ull &a, ull b) {
    asm("add.rn.f32x2 %0, %0, %1;" : "+l"(a) : "l"(b));
}

// ---------- cp.async helpers ----------
__device__ __forceinline__ void cpa16(uint32_t dst, const float* src) {
    asm volatile("cp.async.cg.shared.global [%0], [%1], 16;" :: "r"(dst), "l"(src));
}
__device__ __forceinline__ void cpa_commit() {
    asm volatile("cp.async.commit_group;");
}
template<int N> __device__ __forceinline__ void cpa_wait() {
    asm volatile("cp.async.wait_group %0;" :: "n"(N));
}

// 16KB weight tile (64x64 f32): 8 x 16B per thread (128 threads)
__device__ __forceinline__ void load_w16(float* dst, const float* src, int tid) {
    uint32_t d = (uint32_t)__cvta_generic_to_shared(dst);
    #pragma unroll
    for (int t = 0; t < 8; t++) {
        int w = tid + t * THR;
        cpa16(d + w * 16, src + w * 4);
    }
}
// 32KB codes -> X (128 rows x XSTR): 16 x 16B per thread
__device__ __forceinline__ void load_codes(float* X, const float* src, int tid) {
    uint32_t d = (uint32_t)__cvta_generic_to_shared(X);
    #pragma unroll
    for (int t = 0; t < 16; t++) {
        int w = tid + t * THR;
        int pt = w >> 4, e = w & 15;
        cpa16(d + (pt * XSTR + e * 4) * 4, src + w * 4);
    }
}

// ---------- shared layout (float offsets) ----------
#define OFF_WA    0        // 4096
#define OFF_WB    4096     // 4096
#define OFF_NET   8192     // 128*68 = 8704
#define OFF_X     16896    // 8704 (codes OR relu(h))
#define OFF_OW    25600    // 768
#define SM_FLOATS 26368
#define SM_BYTES  (SM_FLOATS * 4)   // 105472 B -> 2 CTAs/SM

// ---------- conditioning precompute ----------
__global__ void cond_kernel(const float* __restrict__ tf,
                            const float* __restrict__ fc_c_W,
                            const float* __restrict__ fc_c_b) {
    int bi = blockIdx.x;          // b*5 + i
    int b  = bi / NBLK, i = bi % NBLK;
    int h  = threadIdx.x & 63, g = threadIdx.x >> 6;
    const float* W = fc_c_W + (size_t)i * 576 * 64 + 64 * 64 + h;
    const float* t = tf + b * 512;
    float acc = 0.f;
    int k0 = g * 128;
    #pragma unroll 8
    for (int k = k0; k < k0 + 128; k++) acc += t[k] * W[(size_t)k * 64];
    __shared__ float red[256];
    red[threadIdx.x] = acc;
    __syncthreads();
    if (g == 0) {
        float s = red[h] + red[h + 64] + red[h + 128] + red[h + 192] + fc_c_b[i * 64 + h];
        g_cond[bi * 64 + h] = s;
    }
}

// GEMM microtile: 8 points (rows pg+16q) x 8 cols ({og*4..+3}, {32+og*4..+3})
// xb = act base + pg*XSTR ; Wt = weight base + og*4
__device__ __forceinline__ void mm64(ull acc[8][4], const float* __restrict__ xb,
                                     const float* __restrict__ Wt, bool relu_x) {
    #pragma unroll 2
    for (int kk = 0; kk < 64; kk += 4) {
        float xa[8][4];
        #pragma unroll
        for (int q = 0; q < 8; q++)
            *(float4*)xa[q] = *(const float4*)(xb + q * 16 * XSTR + kk);
        if (relu_x) {
            #pragma unroll
            for (int q = 0; q < 8; q++)
                #pragma unroll
                for (int d = 0; d < 4; d++) xa[q][d] = fmaxf(xa[q][d], 0.f);
        }
        #pragma unroll
        for (int d = 0; d < 4; d++) {
            ulonglong2 wA = *(const ulonglong2*)(Wt + (kk + d) * 64);
            ulonglong2 wB = *(const ulonglong2*)(Wt + (kk + d) * 64 + 32);
            #pragma unroll
            for (int q = 0; q < 8; q++) {
                ull xd = dup2(xa[q][d]);
                fma2(acc[q][0], xd, wA.x);
                fma2(acc[q][1], xd, wA.y);
                fma2(acc[q][2], xd, wB.x);
                fma2(acc[q][3], xd, wB.y);
            }
        }
    }
}

__global__ __launch_bounds__(THR, 2)
void mlp_kernel(const float* __restrict__ p, const float* __restrict__ c,
                const float* __restrict__ fc_p_W, const float* __restrict__ fc_p_b,
                const float* __restrict__ fc_c_W,
                const float* __restrict__ blk0_W, const float* __restrict__ blk0_b,
                const float* __restrict__ blk1_W, const float* __restrict__ blk1_b,
                const float* __restrict__ fc_out_W, const float* __restrict__ fc_out_b,
                float* __restrict__ out) {
    extern __shared__ float sm[];
    const int tid = threadIdx.x;
    const int og  = tid & 7;          // cols og*4..+3 and 32+og*4..+3
    const int pg  = tid >> 3;         // rows pg + 16q, q=0..7
    const int base = blockIdx.x * PTS;

    float* WA   = sm + OFF_WA;
    float* WB   = sm + OFF_WB;
    float* NETB = sm + OFF_NET;
    float* X    = sm + OFF_X;

    // prologue async: Wc_0 -> WA (group), codes -> X (group)
    load_w16(WA, fc_c_W, tid); cpa_commit();
    load_codes(X, c + (size_t)base * 64, tid); cpa_commit();

    // out-layer weights -> smem
    for (int w = tid; w < 768; w += THR) sm[OFF_OW + w] = fc_out_W[w];

    float* wrN = NETB + pg * XSTR + og * 4;      // own net tile
    float* wrX = X    + pg * XSTR + og * 4;      // own h tile
    const float* xb = X    + pg * XSTR;
    const float* nb = NETB + pg * XSTR;

    // cond offsets per row
    int cnd[8];
    #pragma unroll
    for (int q = 0; q < 8; q++)
        cnd[q] = ((base + pg + q * 16) / NPTS) * (NBLK * 64) + og * 4;

    // ---- p-layer: net0 = p @ Wp + bp -> NETB (own tile) ----
    {
        ulonglong2 bA = __ldg((const ulonglong2*)(fc_p_b + og * 4));
        ulonglong2 bB = __ldg((const ulonglong2*)(fc_p_b + og * 4 + 32));
        ulonglong2 w[3][2];
        #pragma unroll
        for (int e = 0; e < 3; e++) {
            w[e][0] = __ldg((const ulonglong2*)(fc_p_W + e * 64 + og * 4));
            w[e][1] = __ldg((const ulonglong2*)(fc_p_W + e * 64 + og * 4 + 32));
        }
        #pragma unroll
        for (int q = 0; q < 8; q++) {
            int pt = base + pg + q * 16;
            ull a0 = bA.x, a1 = bA.y, a2 = bB.x, a3 = bB.y;
            #pragma unroll
            for (int e = 0; e < 3; e++) {
                ull xd = dup2(__ldg(p + (size_t)pt * 3 + e));
                fma2(a0, xd, w[e][0].x); fma2(a1, xd, w[e][0].y);
                fma2(a2, xd, w[e][1].x); fma2(a3, xd, w[e][1].y);
            }
            ulonglong2 s0, s1; s0.x = a0; s0.y = a1; s1.x = a2; s1.y = a3;
            *(ulonglong2*)(wrN + q * 16 * XSTR)      = s0;
            *(ulonglong2*)(wrN + q * 16 * XSTR + 32) = s1;
        }
    }

    for (int i = 0; i < NBLK; i++) {
        float* Wcur = (i & 1) ? WB : WA;
        float* Woth = (i & 1) ? WA : WB;

        if (i > 0) { load_codes(X, c + (size_t)base * 64, tid); cpa_commit(); }
        load_w16(Woth, blk0_W + (size_t)i * 4096, tid); cpa_commit();
        cpa_wait<1>();            // Wc_i + codes done; W0 still in flight
        __syncthreads();

        ull acc[8][4];
        // ---- step1: net = net + cond + c @ Wc ----
        #pragma unroll
        for (int q = 0; q < 8; q++) {
            ulonglong2 a = *(const ulonglong2*)(wrN + q * 16 * XSTR);
            ulonglong2 b = *(const ulonglong2*)(wrN + q * 16 * XSTR + 32);
            ulonglong2 c0 = __ldg((const ulonglong2*)(g_cond + cnd[q] + i * 64));
            ulonglong2 c1 = __ldg((const ulonglong2*)(g_cond + cnd[q] + i * 64 + 32));
            acc[q][0] = a.x; acc[q][1] = a.y; acc[q][2] = b.x; acc[q][3] = b.y;
            add2(acc[q][0], c0.x); add2(acc[q][1], c0.y);
            add2(acc[q][2], c1.x); add2(acc[q][3], c1.y);
        }
        mm64(acc, xb, Wcur + og * 4, false);
        #pragma unroll
        for (int q = 0; q < 8; q++) {
            ulonglong2 s0, s1;
            s0.x = acc[q][0]; s0.y = acc[q][1]; s1.x = acc[q][2]; s1.y = acc[q][3];
            *(ulonglong2*)(wrN + q * 16 * XSTR)      = s0;
            *(ulonglong2*)(wrN + q * 16 * XSTR + 32) = s1;
        }
        cpa_wait<0>();            // W0 arrived
        __syncthreads();

        // ---- step2: h = relu(net) @ W0 + b0 ; relu(h) -> X ----
        load_w16(Wcur, blk1_W + (size_t)i * 4096, tid); cpa_commit();  // W1 prefetch
        {
            ulonglong2 bA = __ldg((const ulonglong2*)(blk0_b + i * 64 + og * 4));
            ulonglong2 bB = __ldg((const ulonglong2*)(blk0_b + i * 64 + og * 4 + 32));
            #pragma unroll
            for (int q = 0; q < 8; q++) {
                acc[q][0] = bA.x; acc[q][1] = bA.y; acc[q][2] = bB.x; acc[q][3] = bB.y;
            }
            mm64(acc, nb, Woth + og * 4, true);
            #pragma unroll
            for (int q = 0; q < 8; q++) {
                float2 f0 = unpk(acc[q][0]), f1 = unpk(acc[q][1]);
                float2 f2 = unpk(acc[q][2]), f3 = unpk(acc[q][3]);
                *(float4*)(wrX + q * 16 * XSTR) =
                    make_float4(fmaxf(f0.x, 0.f), fmaxf(f0.y, 0.f),
                                fmaxf(f1.x, 0.f), fmaxf(f1.y, 0.f));
                *(float4*)(wrX + q * 16 * XSTR + 32) =
                    make_float4(fmaxf(f2.x, 0.f), fmaxf(f2.y, 0.f),
                                fmaxf(f3.x, 0.f), fmaxf(f3.y, 0.f));
            }
        }
        cpa_wait<0>();            // W1 arrived
        __syncthreads();

        // ---- step3: net += relu(h) @ W1 + b1 ----
        if (i < NBLK - 1) { load_w16(Woth, fc_c_W + (size_t)(i + 1) * 576 * 64, tid); cpa_commit(); }
        {
            ulonglong2 bA = __ldg((const ulonglong2*)(blk1_b + i * 64 + og * 4));
            ulonglong2 bB = __ldg((const ulonglong2*)(blk1_b + i * 64 + og * 4 + 32));
            #pragma unroll
            for (int q = 0; q < 8; q++) {
                ulonglong2 a = *(const ulonglong2*)(wrN + q * 16 * XSTR);
                ulonglong2 b = *(const ulonglong2*)(wrN + q * 16 * XSTR + 32);
                acc[q][0] = a.x; acc[q][1] = a.y; acc[q][2] = b.x; acc[q][3] = b.y;
                add2(acc[q][0], bA.x); add2(acc[q][1], bA.y);
                add2(acc[q][2], bB.x); add2(acc[q][3], bB.y);
            }
            mm64(acc, xb, Wcur + og * 4, false);
            #pragma unroll
            for (int q = 0; q < 8; q++) {
                ulonglong2 s0, s1;
                s0.x = acc[q][0]; s0.y = acc[q][1]; s1.x = acc[q][2]; s1.y = acc[q][3];
                *(ulonglong2*)(wrN + q * 16 * XSTR)      = s0;
                *(ulonglong2*)(wrN + q * 16 * XSTR + 32) = s1;
            }
        }
        __syncthreads();
    }

    // ---- out = relu(net) @ fc_out_W + fc_out_b ; one point per thread ----
    {
        ull o[6];
        #pragma unroll
        for (int j = 0; j < 6; j++) o[j] = __ldg((const ull*)fc_out_b + j);
        const float* xr = NETB + tid * XSTR;
        #pragma unroll 2
        for (int kk = 0; kk < 64; kk += 4) {
            float xa[4];
            *(float4*)xa = *(const float4*)(xr + kk);
            #pragma unroll
            for (int d = 0; d < 4; d++) {
                ull xd = dup2(fmaxf(xa[d], 0.f));
                const ull* wr = (const ull*)(sm + OFF_OW + (kk + d) * 12);
                #pragma unroll
                for (int j = 0; j < 6; j++) fma2(o[j], xd, wr[j]);
            }
        }
        float2 f0 = unpk(o[0]), f1 = unpk(o[1]), f2 = unpk(o[2]);
        float2 f3 = unpk(o[3]), f4 = unpk(o[4]), f5 = unpk(o[5]);
        float4* dst = (float4*)(out + (size_t)(base + tid) * 12);
        dst[0] = make_float4(f0.x, f0.y, f1.x, f1.y);
        dst[1] = make_float4(f2.x, f2.y, f3.x, f3.y);
        dst[2] = make_float4(f4.x, f4.y, f5.x, f5.y);
    }
}

extern "C" void kernel_launch(void* const* d_in, const int* in_sizes, int n_in,
                              void* d_out, int out_size) {
    const float* p        = (const float*)d_in[0];
    const float* c        = (const float*)d_in[1];
    const float* tf       = (const float*)d_in[2];
    const float* fc_p_W   = (const float*)d_in[3];
    const float* fc_p_b   = (const float*)d_in[4];
    const float* fc_c_W   = (const float*)d_in[5];
    const float* fc_c_b   = (const float*)d_in[6];
    const float* blk0_W   = (const float*)d_in[7];
    const float* blk0_b   = (const float*)d_in[8];
    const float* blk1_W   = (const float*)d_in[9];
    const float* blk1_b   = (const float*)d_in[10];
    const float* fc_out_W = (const float*)d_in[11];
    const float* fc_out_b = (const float*)d_in[12];
    float* out = (float*)d_out;

    cudaFuncSetAttribute(mlp_kernel, cudaFuncAttributeMaxDynamicSharedMemorySize, SM_BYTES);

    cond_kernel<<<8 * NBLK, 256>>>(tf, fc_c_W, fc_c_b);

    int grid = TOT / PTS;   // 3125 CTAs
    mlp_kernel<<<grid, THR, SM_BYTES>>>(p, c, fc_p_W, fc_p_b, fc_c_W,
                                        blk0_W, blk0_b, blk1_W, blk1_b,
                                        fc_out_W, fc_out_b, out);
}

// round 9
// speedup vs baseline: 1.7948x; 1.0334x over previous
#include <cuda_runtime.h>
#include <cstdint>

#define TOT    400000
#define NPTS   50000
#define NBLK   5
#define PTS    128          // points per CTA
#define THR    128          // threads per CTA
#define XSTR   68           // activation row stride (floats)

typedef unsigned long long ull;

// Per-batch conditioning: cond[b][i][h] = task_feature[b] @ fc_c_W[i][64:576,:] + fc_c_b[i]
__device__ float g_cond[8 * NBLK * 64];

// ---------- packed f32x2 helpers ----------
__device__ __forceinline__ ull dup2(float x) {
    ull r; asm("mov.b64 %0, {%1, %1};" : "=l"(r) : "f"(x)); return r;
}
__device__ __forceinline__ float2 unpk(ull a) {
    float2 f; asm("mov.b64 {%0, %1}, %2;" : "=f"(f.x), "=f"(f.y) : "l"(a)); return f;
}
__device__ __forceinline__ void fma2(ull &a, ull x, ull w) {
    asm("fma.rn.f32x2 %0, %1, %2, %0;" : "+l"(a) : "l"(x), "l"(w));
}
__device__ __forceinline__ void add2(ull &a, ull b) {
    asm("add.rn.f32x2 %0, %0, %1;" : "+l"(a) : "l"(b));
}

// ---------- cp.async helpers ----------
__device__ __forceinline__ void cpa16(uint32_t dst, const float* src) {
    asm volatile("cp.async.cg.shared.global [%0], [%1], 16;" :: "r"(dst), "l"(src));
}
__device__ __forceinline__ void cpa_commit() {
    asm volatile("cp.async.commit_group;");
}
template<int N> __device__ __forceinline__ void cpa_wait() {
    asm volatile("cp.async.wait_group %0;" :: "n"(N));
}

// 16KB weight tile (64x64 f32): 8 x 16B per thread (128 threads)
__device__ __forceinline__ void load_w16(float* dst, const float* src, int tid) {
    uint32_t d = (uint32_t)__cvta_generic_to_shared(dst);
    #pragma unroll
    for (int t = 0; t < 8; t++) {
        int w = tid + t * THR;
        cpa16(d + w * 16, src + w * 4);
    }
}
// 32KB codes -> X (128 rows x XSTR): 16 x 16B per thread
__device__ __forceinline__ void load_codes(float* X, const float* src, int tid) {
    uint32_t d = (uint32_t)__cvta_generic_to_shared(X);
    #pragma unroll
    for (int t = 0; t < 16; t++) {
        int w = tid + t * THR;
        int pt = w >> 4, e = w & 15;
        cpa16(d + (pt * XSTR + e * 4) * 4, src + w * 4);
    }
}

// ---------- shared layout (float offsets) ----------
#define OFF_WA    0        // 4096
#define OFF_WB    4096     // 4096
#define OFF_NET   8192     // 128*68 = 8704
#define OFF_X     16896    // 8704 (codes OR relu(h))
#define OFF_OW    25600    // 768
#define OFF_OB    26368    // 16 (12 + pad)
#define OFF_PW    26384    // 192
#define OFF_PB    26576    // 64
#define OFF_CND   26640    // 2 * 320 (cond rows for this CTA's <=2 batches)
#define OFF_B0    27280    // 5*64
#define OFF_B1    27600    // 5*64
#define SM_FLOATS 27920
#define SM_BYTES  (SM_FLOATS * 4)   // 111680 B -> 2 CTAs/SM

// ---------- conditioning precompute ----------
__global__ void cond_kernel(const float* __restrict__ tf,
                            const float* __restrict__ fc_c_W,
                            const float* __restrict__ fc_c_b) {
    int bi = blockIdx.x;          // b*5 + i
    int b  = bi / NBLK, i = bi % NBLK;
    int h  = threadIdx.x & 63, g = threadIdx.x >> 6;
    const float* W = fc_c_W + (size_t)i * 576 * 64 + 64 * 64 + h;
    const float* t = tf + b * 512;
    float acc = 0.f;
    int k0 = g * 128;
    #pragma unroll 8
    for (int k = k0; k < k0 + 128; k++) acc += t[k] * W[(size_t)k * 64];
    __shared__ float red[256];
    red[threadIdx.x] = acc;
    __syncthreads();
    if (g == 0) {
        float s = red[h] + red[h + 64] + red[h + 128] + red[h + 192] + fc_c_b[i * 64 + h];
        g_cond[bi * 64 + h] = s;
    }
}

// GEMM microtile: 8 points (rows pg+16q) x 8 cols ({og*4..+3}, {32+og*4..+3})
// x double-buffered one kk-chunk ahead to hide LDS latency.
__device__ __forceinline__ void mm64(ull acc[8][4], const float* __restrict__ xb,
                                     const float* __restrict__ Wt, bool relu_x) {
    float xa[2][8][4];
    #pragma unroll
    for (int q = 0; q < 8; q++)
        *(float4*)xa[0][q] = *(const float4*)(xb + q * 16 * XSTR);
    #pragma unroll 2
    for (int kc = 0; kc < 16; kc++) {
        const int cur = kc & 1, nxt = cur ^ 1;
        if (kc < 15) {
            #pragma unroll
            for (int q = 0; q < 8; q++)
                *(float4*)xa[nxt][q] = *(const float4*)(xb + q * 16 * XSTR + (kc + 1) * 4);
        }
        #pragma unroll
        for (int d = 0; d < 4; d++) {
            ulonglong2 wA = *(const ulonglong2*)(Wt + (kc * 4 + d) * 64);
            ulonglong2 wB = *(const ulonglong2*)(Wt + (kc * 4 + d) * 64 + 32);
            #pragma unroll
            for (int q = 0; q < 8; q++) {
                float xv = xa[cur][q][d];
                if (relu_x) xv = fmaxf(xv, 0.f);
                ull xd = dup2(xv);
                fma2(acc[q][0], xd, wA.x);
                fma2(acc[q][1], xd, wA.y);
                fma2(acc[q][2], xd, wB.x);
                fma2(acc[q][3], xd, wB.y);
            }
        }
    }
}

__global__ __launch_bounds__(THR, 2)
void mlp_kernel(const float* __restrict__ p, const float* __restrict__ c,
                const float* __restrict__ fc_p_W, const float* __restrict__ fc_p_b,
                const float* __restrict__ fc_c_W,
                const float* __restrict__ blk0_W, const float* __restrict__ blk0_b,
                const float* __restrict__ blk1_W, const float* __restrict__ blk1_b,
                const float* __restrict__ fc_out_W, const float* __restrict__ fc_out_b,
                float* __restrict__ out) {
    extern __shared__ float sm[];
    const int tid = threadIdx.x;
    const int og  = tid & 7;          // cols og*4..+3 and 32+og*4..+3
    const int pg  = tid >> 3;         // rows pg + 16q, q=0..7
    const int base = blockIdx.x * PTS;
    const int bA_id = base / NPTS;
    const int bB_id = (base + PTS - 1) / NPTS;

    float* WA   = sm + OFF_WA;
    float* WB   = sm + OFF_WB;
    float* NETB = sm + OFF_NET;
    float* X    = sm + OFF_X;

    // prologue async: Wc_0 -> WA (group), codes -> X (group)
    load_w16(WA, fc_c_W, tid); cpa_commit();
    load_codes(X, c + (size_t)base * 64, tid); cpa_commit();

    // one-time small operands -> smem (all strided over full range: THR=128!)
    for (int w = tid; w < 768; w += THR) sm[OFF_OW + w] = fc_out_W[w];
    if (tid < 16) sm[OFF_OB + tid] = (tid < 12) ? fc_out_b[tid] : 0.f;
    for (int w = tid; w < 192; w += THR) sm[OFF_PW + w] = fc_p_W[w];
    for (int w = tid; w < 64; w += THR) sm[OFF_PB + w] = fc_p_b[w];
    for (int w = tid; w < 640; w += THR) {          // cond rows for batches bA/bB
        int sel = w / 320, r = w % 320;
        sm[OFF_CND + w] = g_cond[(sel ? bB_id : bA_id) * 320 + r];
    }
    for (int w = tid; w < 320; w += THR) {
        sm[OFF_B0 + w] = blk0_b[w];
        sm[OFF_B1 + w] = blk1_b[w];
    }
    __syncthreads();   // smem params visible (cp.async groups still in flight)

    float* wrN = NETB + pg * XSTR + og * 4;      // own net tile
    float* wrX = X    + pg * XSTR + og * 4;      // own h tile
    const float* xb = X    + pg * XSTR;
    const float* nb = NETB + pg * XSTR;

    // per-row cond smem offsets
    int cnd[8];
    #pragma unroll
    for (int q = 0; q < 8; q++) {
        int sel = ((base + pg + q * 16) / NPTS == bB_id) ? 1 : 0;
        cnd[q] = OFF_CND + sel * 320 + og * 4;
    }

    // ---- p-layer: net0 = p @ Wp + bp -> NETB (own tile) ----
    {
        ulonglong2 bA = *(const ulonglong2*)(sm + OFF_PB + og * 4);
        ulonglong2 bB = *(const ulonglong2*)(sm + OFF_PB + og * 4 + 32);
        ulonglong2 w[3][2];
        #pragma unroll
        for (int e = 0; e < 3; e++) {
            w[e][0] = *(const ulonglong2*)(sm + OFF_PW + e * 64 + og * 4);
            w[e][1] = *(const ulonglong2*)(sm + OFF_PW + e * 64 + og * 4 + 32);
        }
        #pragma unroll
        for (int q = 0; q < 8; q++) {
            int pt = base + pg + q * 16;
            ull a0 = bA.x, a1 = bA.y, a2 = bB.x, a3 = bB.y;
            #pragma unroll
            for (int e = 0; e < 3; e++) {
                ull xd = dup2(__ldg(p + (size_t)pt * 3 + e));
                fma2(a0, xd, w[e][0].x); fma2(a1, xd, w[e][0].y);
                fma2(a2, xd, w[e][1].x); fma2(a3, xd, w[e][1].y);
            }
            ulonglong2 s0, s1; s0.x = a0; s0.y = a1; s1.x = a2; s1.y = a3;
            *(ulonglong2*)(wrN + q * 16 * XSTR)      = s0;
            *(ulonglong2*)(wrN + q * 16 * XSTR + 32) = s1;
        }
    }

    for (int i = 0; i < NBLK; i++) {
        float* Wcur = (i & 1) ? WB : WA;
        float* Woth = (i & 1) ? WA : WB;

        if (i > 0) { load_codes(X, c + (size_t)base * 64, tid); cpa_commit(); }
        load_w16(Woth, blk0_W + (size_t)i * 4096, tid); cpa_commit();
        cpa_wait<1>();            // Wc_i + codes done; W0 still in flight
        __syncthreads();

        ull acc[8][4];
        // ---- step1: net = net + cond + c @ Wc ----
        #pragma unroll
        for (int q = 0; q < 8; q++) {
            ulonglong2 a = *(const ulonglong2*)(wrN + q * 16 * XSTR);
            ulonglong2 b = *(const ulonglong2*)(wrN + q * 16 * XSTR + 32);
            ulonglong2 c0 = *(const ulonglong2*)(sm + cnd[q] + i * 64);
            ulonglong2 c1 = *(const ulonglong2*)(sm + cnd[q] + i * 64 + 32);
            acc[q][0] = a.x; acc[q][1] = a.y; acc[q][2] = b.x; acc[q][3] = b.y;
            add2(acc[q][0], c0.x); add2(acc[q][1], c0.y);
            add2(acc[q][2], c1.x); add2(acc[q][3], c1.y);
        }
        mm64(acc, xb, Wcur + og * 4, false);
        #pragma unroll
        for (int q = 0; q < 8; q++) {
            ulonglong2 s0, s1;
            s0.x = acc[q][0]; s0.y = acc[q][1]; s1.x = acc[q][2]; s1.y = acc[q][3];
            *(ulonglong2*)(wrN + q * 16 * XSTR)      = s0;
            *(ulonglong2*)(wrN + q * 16 * XSTR + 32) = s1;
        }
        cpa_wait<0>();            // W0 arrived
        __syncthreads();

        // ---- step2: h = relu(net) @ W0 + b0 ; relu(h) -> X ----
        load_w16(Wcur, blk1_W + (size_t)i * 4096, tid); cpa_commit();  // W1 prefetch
        {
            ulonglong2 bA = *(const ulonglong2*)(sm + OFF_B0 + i * 64 + og * 4);
            ulonglong2 bB = *(const ulonglong2*)(sm + OFF_B0 + i * 64 + og * 4 + 32);
            #pragma unroll
            for (int q = 0; q < 8; q++) {
                acc[q][0] = bA.x; acc[q][1] = bA.y; acc[q][2] = bB.x; acc[q][3] = bB.y;
            }
            mm64(acc, nb, Woth + og * 4, true);
            #pragma unroll
            for (int q = 0; q < 8; q++) {
                float2 f0 = unpk(acc[q][0]), f1 = unpk(acc[q][1]);
                float2 f2 = unpk(acc[q][2]), f3 = unpk(acc[q][3]);
                *(float4*)(wrX + q * 16 * XSTR) =
                    make_float4(fmaxf(f0.x, 0.f), fmaxf(f0.y, 0.f),
                                fmaxf(f1.x, 0.f), fmaxf(f1.y, 0.f));
                *(float4*)(wrX + q * 16 * XSTR + 32) =
                    make_float4(fmaxf(f2.x, 0.f), fmaxf(f2.y, 0.f),
                                fmaxf(f3.x, 0.f), fmaxf(f3.y, 0.f));
            }
        }
        cpa_wait<0>();            // W1 arrived
        __syncthreads();

        // ---- step3: net += relu(h) @ W1 + b1 ----
        if (i < NBLK - 1) { load_w16(Woth, fc_c_W + (size_t)(i + 1) * 576 * 64, tid); cpa_commit(); }
        {
            ulonglong2 bA = *(const ulonglong2*)(sm + OFF_B1 + i * 64 + og * 4);
            ulonglong2 bB = *(const ulonglong2*)(sm + OFF_B1 + i * 64 + og * 4 + 32);
            #pragma unroll
            for (int q = 0; q < 8; q++) {
                ulonglong2 a = *(const ulonglong2*)(wrN + q * 16 * XSTR);
                ulonglong2 b = *(const ulonglong2*)(wrN + q * 16 * XSTR + 32);
                acc[q][0] = a.x; acc[q][1] = a.y; acc[q][2] = b.x; acc[q][3] = b.y;
                add2(acc[q][0], bA.x); add2(acc[q][1], bA.y);
                add2(acc[q][2], bB.x); add2(acc[q][3], bB.y);
            }
            mm64(acc, xb, Wcur + og * 4, false);
            #pragma unroll
            for (int q = 0; q < 8; q++) {
                ulonglong2 s0, s1;
                s0.x = acc[q][0]; s0.y = acc[q][1]; s1.x = acc[q][2]; s1.y = acc[q][3];
                *(ulonglong2*)(wrN + q * 16 * XSTR)      = s0;
                *(ulonglong2*)(wrN + q * 16 * XSTR + 32) = s1;
            }
        }
        __syncthreads();
    }

    // ---- out = relu(net) @ fc_out_W + fc_out_b ; one point per thread ----
    {
        ull o[6];
        const ull* ob = (const ull*)(sm + OFF_OB);
        #pragma unroll
        for (int j = 0; j < 6; j++) o[j] = ob[j];
        const float* xr = NETB + tid * XSTR;
        #pragma unroll 2
        for (int kk = 0; kk < 64; kk += 4) {
            float xa[4];
            *(float4*)xa = *(const float4*)(xr + kk);
            #pragma unroll
            for (int d = 0; d < 4; d++) {
                ull xd = dup2(fmaxf(xa[d], 0.f));
                const ull* wr = (const ull*)(sm + OFF_OW + (kk + d) * 12);
                #pragma unroll
                for (int j = 0; j < 6; j++) fma2(o[j], xd, wr[j]);
            }
        }
        float2 f0 = unpk(o[0]), f1 = unpk(o[1]), f2 = unpk(o[2]);
        float2 f3 = unpk(o[3]), f4 = unpk(o[4]), f5 = unpk(o[5]);
        float4* dst = (float4*)(out + (size_t)(base + tid) * 12);
        dst[0] = make_float4(f0.x, f0.y, f1.x, f1.y);
        dst[1] = make_float4(f2.x, f2.y, f3.x, f3.y);
        dst[2] = make_float4(f4.x, f4.y, f5.x, f5.y);
    }
}

extern "C" void kernel_launch(void* const* d_in, const int* in_sizes, int n_in,
                              void* d_out, int out_size) {
    const float* p        = (const float*)d_in[0];
    const float* c        = (const float*)d_in[1];
    const float* tf       = (const float*)d_in[2];
    const float* fc_p_W   = (const float*)d_in[3];
    const float* fc_p_b   = (const float*)d_in[4];
    const float* fc_c_W   = (const float*)d_in[5];
    const float* fc_c_b   = (const float*)d_in[6];
    const float* blk0_W   = (const float*)d_in[7];
    const float* blk0_b   = (const float*)d_in[8];
    const float* blk1_W   = (const float*)d_in[9];
    const float* blk1_b   = (const float*)d_in[10];
    const float* fc_out_W = (const float*)d_in[11];
    const float* fc_out_b = (const float*)d_in[12];
    float* out = (float*)d_out;

    cudaFuncSetAttribute(mlp_kernel, cudaFuncAttributeMaxDynamicSharedMemorySize, SM_BYTES);

    cond_kernel<<<8 * NBLK, 256>>>(tf, fc_c_W, fc_c_b);

    int grid = TOT / PTS;   // 3125 CTAs
    mlp_kernel<<<grid, THR, SM_BYTES>>>(p, c, fc_p_W, fc_p_b, fc_c_W,
                                        blk0_W, blk0_b, blk1_W, blk1_b,
                                        fc_out_W, fc_out_b, out);
}